// round 1
// baseline (speedup 1.0000x reference)
#include <cuda_runtime.h>

// Scratch for the per-batch 128-float result vector (no cudaMalloc allowed).
__device__ __align__(16) float g_v[32 * 128];

// Kernel A: one block per batch.
// Phase 1: xbar[f] = mean over 4096 nodes of x[b,n,f]   (12 values)
// Phase 2: t[h]    = xbar @ W1[:,h] + b1[h]             (256 values)
// Phase 3: v[o]    = t @ W2[:,o]   + b2[o]              (128 values) -> g_v
__global__ __launch_bounds__(384) void gcn_reduce_gemm(
    const float* __restrict__ x,   // [32, 4096, 12]
    const float* __restrict__ W1,  // [12, 256]
    const float* __restrict__ b1,  // [256]
    const float* __restrict__ W2,  // [256, 128]
    const float* __restrict__ b2)  // [128]
{
    const int b   = blockIdx.x;           // 0..31
    const int tid = threadIdx.x;          // 0..383
    const int f   = tid % 12;             // fixed per thread (384 % 12 == 0)
    const int slot = tid / 12;            // 0..31

    __shared__ float red[12][32];
    __shared__ float xbar[12];
    __shared__ float t[256];

    // ---- Phase 1: strided, fully coalesced reduction over 4096*12 floats ----
    const float* xb = x + (size_t)b * 4096 * 12;
    float acc = 0.f;
    #pragma unroll 4
    for (int i = tid; i < 4096 * 12; i += 384)
        acc += xb[i];
    red[f][slot] = acc;
    __syncthreads();

    if (tid < 12) {
        float s = 0.f;
        #pragma unroll
        for (int k = 0; k < 32; ++k) s += red[tid][k];
        xbar[tid] = s * (1.0f / 4096.0f);
    }
    __syncthreads();

    // ---- Phase 2: t = xbar @ W1 + b1  (12x256) ----
    if (tid < 256) {
        float s = b1[tid];
        #pragma unroll
        for (int ff = 0; ff < 12; ++ff)
            s += xbar[ff] * W1[ff * 256 + tid];
        t[tid] = s;
    }
    __syncthreads();

    // ---- Phase 3: v = t @ W2 + b2  (256x128) ----
    if (tid < 128) {
        float s = b2[tid];
        #pragma unroll 8
        for (int h = 0; h < 256; ++h)
            s += t[h] * W2[h * 128 + tid];
        g_v[b * 128 + tid] = s;
    }
}

// Kernel B: broadcast v[b] (128 floats = 32 float4) to all 4096 node rows.
// Total: 32 * 4096 * 32 = 4,194,304 float4 stores (67 MB). Pure write-bound.
__global__ __launch_bounds__(256) void gcn_broadcast(float4* __restrict__ out)
{
    const float4* __restrict__ v4 = reinterpret_cast<const float4*>(g_v);
    const int total = 32 * 4096 * 32;               // float4 count
    const int stride = gridDim.x * blockDim.x;
    for (int g = blockIdx.x * blockDim.x + threadIdx.x; g < total; g += stride) {
        const int bidx = g >> 17;                   // / (4096*32)
        const int o4   = g & 31;                    // % 32
        out[g] = __ldg(&v4[(bidx << 5) + o4]);
    }
}

extern "C" void kernel_launch(void* const* d_in, const int* in_sizes, int n_in,
                              void* d_out, int out_size)
{
    const float* x  = (const float*)d_in[0];  // [32,4096,12]
    const float* W1 = (const float*)d_in[1];  // [12,256]
    const float* b1 = (const float*)d_in[2];  // [256]
    const float* W2 = (const float*)d_in[3];  // [256,128]
    const float* b2 = (const float*)d_in[4];  // [128]

    gcn_reduce_gemm<<<32, 384>>>(x, W1, b1, W2, b2);
    gcn_broadcast<<<2048, 256>>>((float4*)d_out);
}

// round 2
// speedup vs baseline: 1.1400x; 1.1400x over previous
#include <cuda_runtime.h>

// Scratch (no cudaMalloc allowed): per-(batch,slice) partial sums and the
// per-batch 128-float result vector.
__device__ float g_partial[512 * 12];          // [32 batches][16 slices][12 feats]
__device__ __align__(16) float g_v[32 * 128];  // [32 batches][128 outs]

// ---------------------------------------------------------------------------
// Stage 1: 512 blocks (16 slices per batch). Each block reduces 256 rows x 12
// feats = 3072 floats (coalesced: thread tid handles float index tid, tid+384,
// ... so feature f = tid%12 is fixed per thread since 384 % 12 == 0).
// Deterministic (no float atomics).
// ---------------------------------------------------------------------------
__global__ __launch_bounds__(384) void gcn_reduce_partial(
    const float* __restrict__ x)   // [32, 4096, 12]
{
    const int blk   = blockIdx.x;        // 0..511
    const int batch = blk >> 4;          // /16
    const int slice = blk & 15;
    const int tid   = threadIdx.x;       // 0..383
    const int f     = tid % 12;
    const int slot  = tid / 12;          // 0..31

    const float* p = x + ((size_t)batch * 4096 + (size_t)slice * 256) * 12;

    float acc = 0.f;
    #pragma unroll
    for (int i = 0; i < 8; ++i)          // 8 * 384 = 3072 floats
        acc += p[tid + i * 384];

    __shared__ float red[12][32];
    red[f][slot] = acc;
    __syncthreads();

    if (tid < 12) {
        float s = 0.f;
        #pragma unroll
        for (int k = 0; k < 32; ++k) s += red[tid][k];
        g_partial[blk * 12 + tid] = s;
    }
}

// ---------------------------------------------------------------------------
// Stage 2: one block per batch. Combine 16 partials -> xbar, then the tiny
// 12->256->128 chain, write v[b] to g_v. Negligible work.
// ---------------------------------------------------------------------------
__global__ __launch_bounds__(256) void gcn_tiny_mlp(
    const float* __restrict__ W1,  // [12, 256]
    const float* __restrict__ b1,  // [256]
    const float* __restrict__ W2,  // [256, 128]
    const float* __restrict__ b2)  // [128]
{
    const int b   = blockIdx.x;    // 0..31
    const int tid = threadIdx.x;   // 0..255

    __shared__ float xbar[12];
    __shared__ float t[256];

    if (tid < 12) {
        float s = 0.f;
        #pragma unroll
        for (int k = 0; k < 16; ++k)
            s += g_partial[(b * 16 + k) * 12 + tid];
        xbar[tid] = s * (1.0f / 4096.0f);
    }
    __syncthreads();

    {   // t = xbar @ W1 + b1  (all 256 threads)
        float s = b1[tid];
        #pragma unroll
        for (int ff = 0; ff < 12; ++ff)
            s += xbar[ff] * W1[ff * 256 + tid];
        t[tid] = s;
    }
    __syncthreads();

    if (tid < 128) {  // v = t @ W2 + b2
        float s = b2[tid];
        #pragma unroll 8
        for (int h = 0; h < 256; ++h)
            s += t[h] * W2[h * 128 + tid];
        g_v[b * 128 + tid] = s;
    }
}

// ---------------------------------------------------------------------------
// Stage 3: broadcast. One warp owns 8 consecutive rows of ONE batch; each lane
// loads its float4 of v once, then issues 8 unrolled STG.128 (each warp store
// = 512 B contiguous = one full row). 131072 rows total -> 16384 warps ->
// 2048 blocks x 256 threads. Inner loop is pure STG + IADD: store-issue bound.
// ---------------------------------------------------------------------------
__global__ __launch_bounds__(256) void gcn_broadcast(float4* __restrict__ out)
{
    const int gw    = (blockIdx.x * 256 + threadIdx.x) >> 5;  // global warp 0..16383
    const int lane  = threadIdx.x & 31;
    const int batch = gw >> 9;            // / 512 (512 warps per batch)
    const int row0  = (gw & 511) << 3;    // * 8 rows

    const float4* __restrict__ v4 = reinterpret_cast<const float4*>(g_v);
    const float4 val = v4[(batch << 5) + lane];

    float4* base = out + ((size_t)batch * 4096 + row0) * 32 + lane;
    #pragma unroll
    for (int r = 0; r < 8; ++r)
        base[r * 32] = val;
}

extern "C" void kernel_launch(void* const* d_in, const int* in_sizes, int n_in,
                              void* d_out, int out_size)
{
    const float* x  = (const float*)d_in[0];  // [32,4096,12]
    const float* W1 = (const float*)d_in[1];  // [12,256]
    const float* b1 = (const float*)d_in[2];  // [256]
    const float* W2 = (const float*)d_in[3];  // [256,128]
    const float* b2 = (const float*)d_in[4];  // [128]

    gcn_reduce_partial<<<512, 384>>>(x);
    gcn_tiny_mlp<<<32, 256>>>(W1, b1, W2, b2);
    gcn_broadcast<<<2048, 256>>>((float4*)d_out);
}

// round 3
// speedup vs baseline: 1.1425x; 1.0022x over previous
#include <cuda_runtime.h>

// Scratch (no cudaMalloc allowed): per-(batch,slice) partial sums and the
// per-batch 128-float result vector.
__device__ float g_partial[512 * 12];          // [32 batches][16 slices][12 feats]
__device__ __align__(16) float g_v[32 * 128];  // [32 batches][128 outs]

// ---------------------------------------------------------------------------
// Stage 1: 512 blocks (16 slices per batch). Each block reduces 256 rows x 12
// feats = 3072 floats (coalesced: thread tid handles float index tid, tid+384,
// ... so feature f = tid%12 is fixed per thread since 384 % 12 == 0).
// Deterministic (no float atomics).
// ---------------------------------------------------------------------------
__global__ __launch_bounds__(384) void gcn_reduce_partial(
    const float* __restrict__ x)   // [32, 4096, 12]
{
    const int blk   = blockIdx.x;        // 0..511
    const int batch = blk >> 4;          // /16
    const int slice = blk & 15;
    const int tid   = threadIdx.x;       // 0..383
    const int f     = tid % 12;
    const int slot  = tid / 12;          // 0..31

    const float* p = x + ((size_t)batch * 4096 + (size_t)slice * 256) * 12;

    float acc = 0.f;
    #pragma unroll
    for (int i = 0; i < 8; ++i)          // 8 * 384 = 3072 floats
        acc += p[tid + i * 384];

    __shared__ float red[12][32];
    red[f][slot] = acc;
    __syncthreads();

    if (tid < 12) {
        float s = 0.f;
        #pragma unroll
        for (int k = 0; k < 32; ++k) s += red[tid][k];
        g_partial[blk * 12 + tid] = s;
    }
}

// ---------------------------------------------------------------------------
// Stage 2: one block per batch. Combine 16 partials -> xbar, then the tiny
// 12->256->128 chain, write v[b] to g_v. Negligible work.
// ---------------------------------------------------------------------------
__global__ __launch_bounds__(256) void gcn_tiny_mlp(
    const float* __restrict__ W1,  // [12, 256]
    const float* __restrict__ b1,  // [256]
    const float* __restrict__ W2,  // [256, 128]
    const float* __restrict__ b2)  // [128]
{
    const int b   = blockIdx.x;    // 0..31
    const int tid = threadIdx.x;   // 0..255

    __shared__ float xbar[12];
    __shared__ float t[256];

    if (tid < 12) {
        float s = 0.f;
        #pragma unroll
        for (int k = 0; k < 16; ++k)
            s += g_partial[(b * 16 + k) * 12 + tid];
        xbar[tid] = s * (1.0f / 4096.0f);
    }
    __syncthreads();

    {   // t = xbar @ W1 + b1  (all 256 threads)
        float s = b1[tid];
        #pragma unroll
        for (int ff = 0; ff < 12; ++ff)
            s += xbar[ff] * W1[ff * 256 + tid];
        t[tid] = s;
    }
    __syncthreads();

    if (tid < 128) {  // v = t @ W2 + b2
        float s = b2[tid];
        #pragma unroll 8
        for (int h = 0; h < 256; ++h)
            s += t[h] * W2[h * 128 + tid];
        g_v[b * 128 + tid] = s;
    }
}

// ---------------------------------------------------------------------------
// Stage 3: broadcast. One warp owns 8 consecutive rows of ONE batch; each lane
// loads its float4 of v once, then issues 8 unrolled STG.128 (each warp store
// = 512 B contiguous = one full row). 131072 rows total -> 16384 warps ->
// 2048 blocks x 256 threads. Inner loop is pure STG + IADD: store-issue bound.
// ---------------------------------------------------------------------------
__global__ __launch_bounds__(256) void gcn_broadcast(float4* __restrict__ out)
{
    const int gw    = (blockIdx.x * 256 + threadIdx.x) >> 5;  // global warp 0..16383
    const int lane  = threadIdx.x & 31;
    const int batch = gw >> 9;            // / 512 (512 warps per batch)
    const int row0  = (gw & 511) << 3;    // * 8 rows

    const float4* __restrict__ v4 = reinterpret_cast<const float4*>(g_v);
    const float4 val = v4[(batch << 5) + lane];

    float4* base = out + ((size_t)batch * 4096 + row0) * 32 + lane;
    #pragma unroll
    for (int r = 0; r < 8; ++r)
        base[r * 32] = val;
}

extern "C" void kernel_launch(void* const* d_in, const int* in_sizes, int n_in,
                              void* d_out, int out_size)
{
    const float* x  = (const float*)d_in[0];  // [32,4096,12]
    const float* W1 = (const float*)d_in[1];  // [12,256]
    const float* b1 = (const float*)d_in[2];  // [256]
    const float* W2 = (const float*)d_in[3];  // [256,128]
    const float* b2 = (const float*)d_in[4];  // [128]

    gcn_reduce_partial<<<512, 384>>>(x);
    gcn_tiny_mlp<<<32, 256>>>(W1, b1, W2, b2);
    gcn_broadcast<<<2048, 256>>>((float4*)d_out);
}

// round 4
// speedup vs baseline: 1.1463x; 1.0033x over previous
#include <cuda_runtime.h>

// Scratch (no cudaMalloc allowed): per-(batch,slice) partial sums and the
// per-batch 128-float result vector.
__device__ float g_partial[512 * 12];          // [32 batches][16 slices][12 feats]
__device__ __align__(16) float g_v[32 * 128];  // [32 batches][128 outs]

// ---------------------------------------------------------------------------
// Stage 1: 512 blocks (16 slices per batch). Each block reduces 256 rows x 12
// feats = 3072 floats (coalesced: thread tid handles float index tid, tid+384,
// ... so feature f = tid%12 is fixed per thread since 384 % 12 == 0).
// Deterministic (no float atomics).
// ---------------------------------------------------------------------------
__global__ __launch_bounds__(384) void gcn_reduce_partial(
    const float* __restrict__ x)   // [32, 4096, 12]
{
    const int blk   = blockIdx.x;        // 0..511
    const int batch = blk >> 4;          // /16
    const int slice = blk & 15;
    const int tid   = threadIdx.x;       // 0..383
    const int f     = tid % 12;
    const int slot  = tid / 12;          // 0..31

    const float* p = x + ((size_t)batch * 4096 + (size_t)slice * 256) * 12;

    float acc = 0.f;
    #pragma unroll
    for (int i = 0; i < 8; ++i)          // 8 * 384 = 3072 floats
        acc += p[tid + i * 384];

    __shared__ float red[12][32];
    red[f][slot] = acc;
    __syncthreads();

    if (tid < 12) {
        float s = 0.f;
        #pragma unroll
        for (int k = 0; k < 32; ++k) s += red[tid][k];
        g_partial[blk * 12 + tid] = s;
    }
}

// ---------------------------------------------------------------------------
// Stage 2: one block per batch. Combine 16 partials -> xbar, then the tiny
// 12->256->128 chain, write v[b] to g_v. Negligible work.
// ---------------------------------------------------------------------------
__global__ __launch_bounds__(256) void gcn_tiny_mlp(
    const float* __restrict__ W1,  // [12, 256]
    const float* __restrict__ b1,  // [256]
    const float* __restrict__ W2,  // [256, 128]
    const float* __restrict__ b2)  // [128]
{
    const int b   = blockIdx.x;    // 0..31
    const int tid = threadIdx.x;   // 0..255

    __shared__ float xbar[12];
    __shared__ float t[256];

    if (tid < 12) {
        float s = 0.f;
        #pragma unroll
        for (int k = 0; k < 16; ++k)
            s += g_partial[(b * 16 + k) * 12 + tid];
        xbar[tid] = s * (1.0f / 4096.0f);
    }
    __syncthreads();

    {   // t = xbar @ W1 + b1  (all 256 threads)
        float s = b1[tid];
        #pragma unroll
        for (int ff = 0; ff < 12; ++ff)
            s += xbar[ff] * W1[ff * 256 + tid];
        t[tid] = s;
    }
    __syncthreads();

    if (tid < 128) {  // v = t @ W2 + b2
        float s = b2[tid];
        #pragma unroll 8
        for (int h = 0; h < 256; ++h)
            s += t[h] * W2[h * 128 + tid];
        g_v[b * 128 + tid] = s;
    }
}

// ---------------------------------------------------------------------------
// Stage 3: broadcast. One warp owns 8 consecutive rows of ONE batch; each lane
// loads its float4 of v once, then issues 8 unrolled STG.128 (each warp store
// = 512 B contiguous = one full row). 131072 rows total -> 16384 warps ->
// 2048 blocks x 256 threads. Inner loop is pure STG + IADD: store-issue bound.
// ---------------------------------------------------------------------------
__global__ __launch_bounds__(256) void gcn_broadcast(float4* __restrict__ out)
{
    const int gw    = (blockIdx.x * 256 + threadIdx.x) >> 5;  // global warp 0..16383
    const int lane  = threadIdx.x & 31;
    const int batch = gw >> 9;            // / 512 (512 warps per batch)
    const int row0  = (gw & 511) << 3;    // * 8 rows

    const float4* __restrict__ v4 = reinterpret_cast<const float4*>(g_v);
    const float4 val = v4[(batch << 5) + lane];

    float4* base = out + ((size_t)batch * 4096 + row0) * 32 + lane;
    #pragma unroll
    for (int r = 0; r < 8; ++r)
        base[r * 32] = val;
}

extern "C" void kernel_launch(void* const* d_in, const int* in_sizes, int n_in,
                              void* d_out, int out_size)
{
    const float* x  = (const float*)d_in[0];  // [32,4096,12]
    const float* W1 = (const float*)d_in[1];  // [12,256]
    const float* b1 = (const float*)d_in[2];  // [256]
    const float* W2 = (const float*)d_in[3];  // [256,128]
    const float* b2 = (const float*)d_in[4];  // [128]

    gcn_reduce_partial<<<512, 384>>>(x);
    gcn_tiny_mlp<<<32, 256>>>(W1, b1, W2, b2);
    gcn_broadcast<<<2048, 256>>>((float4*)d_out);
}